// round 2
// baseline (speedup 1.0000x reference)
#include <cuda_runtime.h>

// ---------------------------------------------------------------------------
// BiLSTM fp32, now using Blackwell packed fp32x2 FMA (fma.rn.f32x2 -> FFMA2),
// which doubles the fp32 MAC rate per issue slot with full fp32 precision.
//
// Pipeline (5 launches):
//   1. gemm_xz(layer=0)   2. rec(layer=0)   3. gemm_xz(layer=1)
//   4. rec(layer=1)       5. merge
// ---------------------------------------------------------------------------

#define B_DIM 128

// ---- scratch (device globals; allocation is forbidden) --------------------
__device__ float g_xz[2][33554432];     // [dir][(b*T+t)*1024 + col]
__device__ float g_out1[2][8388608];    // [dir][(b*T+t)*256 + u]
__device__ float g_out2[2][8388608];
__device__ float g_h[2][2][B_DIM * 256];
__device__ unsigned g_cnt[16];
__device__ volatile unsigned g_sns[16];

typedef unsigned long long ull;

__device__ __forceinline__ ull ffma2(ull a, ull b, ull c) {
    ull d;
    asm("fma.rn.f32x2 %0, %1, %2, %3;" : "=l"(d) : "l"(a), "l"(b), "l"(c));
    return d;
}
__device__ __forceinline__ ull pack2(float lo, float hi) {
    ull r;
    asm("mov.b64 %0, {%1, %2};" : "=l"(r) : "r"(__float_as_uint(lo)), "r"(__float_as_uint(hi)));
    return r;
}
__device__ __forceinline__ ull dup2(float v) { return pack2(v, v); }
__device__ __forceinline__ float2 unpack2(ull v) {
    unsigned lo, hi;
    asm("mov.b64 {%0, %1}, %2;" : "=r"(lo), "=r"(hi) : "l"(v));
    return make_float2(__uint_as_float(lo), __uint_as_float(hi));
}

__device__ __forceinline__ float sigf(float x) {
    return 1.0f / (1.0f + __expf(-x));
}
__device__ __forceinline__ float tanhf_fast(float x) {
    return 2.0f / (1.0f + __expf(-2.0f * x)) - 1.0f;
}

// ---------------------------------------------------------------------------
// GEMM: C[M=32768, N=1024] = A[M,256] @ W[256,1024] + bias
// BM=128, BN=64, BK=16, 256 threads. Per-thread: 8 rows (4 row-pairs) x 4 cols.
// A stored k-major (transposed) scalar -> adjacent rows load as f32x2 pairs.
// B stored duplicated {b,b} pairs. Inner: 16 FFMA2 per kk (= 32 MACs).
// ---------------------------------------------------------------------------
__global__ __launch_bounds__(256) void gemm_xz_kernel(
    const float* __restrict__ x,
    const float* __restrict__ kfw, const float* __restrict__ kbw,
    const float* __restrict__ bfw, const float* __restrict__ bbw,
    int layer)
{
    const int dir = blockIdx.z;
    const float* __restrict__ A = (layer == 0) ? x : g_out1[dir];
    const float* __restrict__ W = (dir ? kbw : kfw) + layer * 262144;
    const float* __restrict__ bias = (dir ? bbw : bfw) + layer * 1024;
    float* __restrict__ C = g_xz[dir];

    const int m0 = blockIdx.y * 128;
    const int n0 = blockIdx.x * 64;

    __shared__ float As[16 * 132];     // [k][row], scalar
    __shared__ ull   Bsd[16 * 66];     // [k][col] duplicated pairs

    const int tid = threadIdx.x;
    const int tx = tid & 15;          // col group: 4*tx..4*tx+3
    const int ty = tid >> 4;          // row group: 8*ty..8*ty+7
    const int ar = tid >> 2;
    const int ac = (tid & 3) << 2;
    const int br = tid >> 4;
    const int bc = (tid & 15) << 2;

    ull acc[4][4];   // [row-pair][col]
#pragma unroll
    for (int p = 0; p < 4; p++)
#pragma unroll
        for (int c = 0; c < 4; c++) acc[p][c] = 0ull;

    for (int k0 = 0; k0 < 256; k0 += 16) {
        float4 a0 = *(const float4*)&A[(m0 + ar) * 256 + k0 + ac];
        float4 a1 = *(const float4*)&A[(m0 + ar + 64) * 256 + k0 + ac];
        float4 b0 = *(const float4*)&W[(k0 + br) * 1024 + n0 + bc];
        __syncthreads();
        As[(ac + 0) * 132 + ar] = a0.x; As[(ac + 1) * 132 + ar] = a0.y;
        As[(ac + 2) * 132 + ar] = a0.z; As[(ac + 3) * 132 + ar] = a0.w;
        As[(ac + 0) * 132 + ar + 64] = a1.x; As[(ac + 1) * 132 + ar + 64] = a1.y;
        As[(ac + 2) * 132 + ar + 64] = a1.z; As[(ac + 3) * 132 + ar + 64] = a1.w;
        Bsd[br * 66 + bc + 0] = dup2(b0.x);
        Bsd[br * 66 + bc + 1] = dup2(b0.y);
        Bsd[br * 66 + bc + 2] = dup2(b0.z);
        Bsd[br * 66 + bc + 3] = dup2(b0.w);
        __syncthreads();
#pragma unroll
        for (int kk = 0; kk < 16; kk++) {
            ulonglong2 ap0 = *(const ulonglong2*)&As[kk * 132 + ty * 8];
            ulonglong2 ap1 = *(const ulonglong2*)&As[kk * 132 + ty * 8 + 4];
            ulonglong2 bd0 = *(const ulonglong2*)&Bsd[kk * 66 + tx * 4];
            ulonglong2 bd1 = *(const ulonglong2*)&Bsd[kk * 66 + tx * 4 + 2];
            ull ap[4] = {ap0.x, ap0.y, ap1.x, ap1.y};
            ull bd[4] = {bd0.x, bd0.y, bd1.x, bd1.y};
#pragma unroll
            for (int p = 0; p < 4; p++)
#pragma unroll
                for (int c = 0; c < 4; c++)
                    acc[p][c] = ffma2(ap[p], bd[c], acc[p][c]);
        }
    }

    float4 bv = *(const float4*)&bias[n0 + tx * 4];
    float bb[4] = {bv.x, bv.y, bv.z, bv.w};
#pragma unroll
    for (int p = 0; p < 4; p++) {
        float2 u[4];
#pragma unroll
        for (int c = 0; c < 4; c++) u[c] = unpack2(acc[p][c]);
        float4 lo, hi;
        lo.x = u[0].x + bb[0]; lo.y = u[1].x + bb[1];
        lo.z = u[2].x + bb[2]; lo.w = u[3].x + bb[3];
        hi.x = u[0].y + bb[0]; hi.y = u[1].y + bb[1];
        hi.z = u[2].y + bb[2]; hi.w = u[3].y + bb[3];
        *(float4*)&C[(m0 + ty * 8 + 2 * p + 0) * 1024 + n0 + tx * 4] = lo;
        *(float4*)&C[(m0 + ty * 8 + 2 * p + 1) * 1024 + n0 + tx * 4] = hi;
    }
}

// ---------------------------------------------------------------------------
// Persistent recurrence kernel (FFMA2).
// 128 CTAs = 2 dirs x 8 batch-tiles(16 rows) x 8 unit-tiles(32 units x 4 gates).
// 128 threads = 4 warps. Warp w owns gate w (cols w*32..w*32+31 of the tile).
// Thread: lane&7 -> 4-unit col group, lane>>3 -> 4-row group.
// Inner loop per k: 1 LDS.128 (4 h scalars) + 4 dup-packs + 1 LDS.128 (R pair
// quad) + 8 FFMA2  (32 MACs).
// ---------------------------------------------------------------------------
#define REC_SMEM_FLOATS (32768 + 5120 + 2112 + 544)
#define REC_SMEM_BYTES (REC_SMEM_FLOATS * 4)

__device__ __forceinline__ void group_barrier(int grp, unsigned* s_sense) {
    __syncthreads();
    if (threadIdx.x == 0) {
        unsigned ls = *s_sense ^ 1u;
        *s_sense = ls;
        __threadfence();
        unsigned v = atomicAdd(&g_cnt[grp], 1u);
        if (v == 7u) {
            g_cnt[grp] = 0u;
            __threadfence();
            g_sns[grp] = ls;
        } else {
            while (g_sns[grp] != ls) { }
        }
    }
    __syncthreads();
}

__global__ __launch_bounds__(128) void rec_kernel(
    const float* __restrict__ rfw, const float* __restrict__ rbw, int layer)
{
    extern __shared__ float sm[];
    float* Rs  = sm;               // [256][128]  permuted (gate-block) cols
    float* hs  = Rs + 32768;       // [256][20]   h transposed, scalar
    float* zs2 = hs + 5120;        // [16][132]   z exchange, row-major
    float* cs  = zs2 + 2112;       // [32][17]    cell state

    const int bx  = blockIdx.x;
    const int dir = bx >> 6;
    const int gt  = bx & 7;
    const int grp = bx >> 3;            // dir*8 + batch_tile
    const int b0  = ((bx >> 3) & 7) * 16;
    const int u0  = gt * 32;

    const float* __restrict__ R   = (dir ? rbw : rfw) + layer * 262144;
    const float* __restrict__ xz  = g_xz[dir];
    float* __restrict__ outp      = layer ? g_out2[dir] : g_out1[dir];
    float* __restrict__ hbuf0     = g_h[dir][0];
    float* __restrict__ hbuf1     = g_h[dir][1];

    const int tid  = threadIdx.x;
    const int lane = tid & 31;
    const int w    = tid >> 5;          // warp = gate index

    __shared__ unsigned s_sense;
    if (tid == 0) s_sense = g_sns[grp];

    // Load R slice, permuted: tile col ci = q*32+uu <- original col q*256+u0+uu
    for (int idx = tid; idx < 256 * 128; idx += 128) {
        int k  = idx >> 7;
        int ci = idx & 127;
        int q  = ci >> 5;
        int uu = ci & 31;
        Rs[idx] = R[k * 1024 + q * 256 + u0 + uu];
    }

    // Init c = 0 and h phase0 = 0 (this CTA's slice)
    {
        int uu = lane;
#pragma unroll
        for (int j = 0; j < 4; j++) {
            int bi = 4 * w + j;
            cs[uu * 17 + bi] = 0.0f;
            hbuf0[(b0 + bi) * 256 + u0 + uu] = 0.0f;
        }
    }
    group_barrier(grp, &s_sense);

    const int cg   = (lane & 7) * 4;        // col group within 32-unit block
    const int ci0  = w * 32 + cg;           // tile col base
    const int r0   = (lane >> 3) * 4;       // row base (0,4,8,12)
    const int gcol = w * 256 + u0 + cg;     // global xz col base

    for (int s = 0; s < 256; s++) {
        const int t = dir ? (255 - s) : s;
        const float* __restrict__ hprev = (s & 1) ? hbuf1 : hbuf0;
        float* __restrict__ hnext = (s & 1) ? hbuf0 : hbuf1;

        // Prefetch xz into accumulators (independent of h)
        ull acc[4][2];
#pragma unroll
        for (int r = 0; r < 4; r++) {
            float4 v = *(const float4*)&xz[((b0 + r0 + r) * 256 + t) * 1024 + gcol];
            acc[r][0] = pack2(v.x, v.y);
            acc[r][1] = pack2(v.z, v.w);
        }

        // Load h tile (16x256) transposed into SMEM (L2-coherent loads)
#pragma unroll
        for (int m = 0; m < 4; m++) {
            int bi = w + 4 * m;
            const float* src = hprev + (b0 + bi) * 256;
#pragma unroll
            for (int j = 0; j < 8; j++) {
                int k = lane + 32 * j;
                hs[k * 20 + bi] = __ldcg(src + k);
            }
        }
        __syncthreads();

        // z += h @ R_slice   (16 rows x 128 cols x 256 k), FFMA2
#pragma unroll 4
        for (int k = 0; k < 256; k++) {
            float4 h4 = *(const float4*)&hs[k * 20 + r0];
            ulonglong2 rv = *(const ulonglong2*)&Rs[k * 128 + ci0];
            ull hd0 = dup2(h4.x), hd1 = dup2(h4.y);
            ull hd2 = dup2(h4.z), hd3 = dup2(h4.w);
            acc[0][0] = ffma2(hd0, rv.x, acc[0][0]);
            acc[0][1] = ffma2(hd0, rv.y, acc[0][1]);
            acc[1][0] = ffma2(hd1, rv.x, acc[1][0]);
            acc[1][1] = ffma2(hd1, rv.y, acc[1][1]);
            acc[2][0] = ffma2(hd2, rv.x, acc[2][0]);
            acc[2][1] = ffma2(hd2, rv.y, acc[2][1]);
            acc[3][0] = ffma2(hd3, rv.x, acc[3][0]);
            acc[3][1] = ffma2(hd3, rv.y, acc[3][1]);
        }

        // Stash z to SMEM for gate regrouping
#pragma unroll
        for (int r = 0; r < 4; r++) {
            float2 p0 = unpack2(acc[r][0]);
            float2 p1 = unpack2(acc[r][1]);
            *(float4*)&zs2[(r0 + r) * 132 + ci0] = make_float4(p0.x, p0.y, p1.x, p1.y);
        }
        __syncthreads();

        // Gate nonlinearities + state update (thread owns unit uu=lane, 4 rows)
        {
            int uu = lane;
#pragma unroll
            for (int j = 0; j < 4; j++) {
                int bi = 4 * w + j;
                float zi = zs2[bi * 132 + uu];
                float zf = zs2[bi * 132 + 32 + uu];
                float zg = zs2[bi * 132 + 64 + uu];
                float zo = zs2[bi * 132 + 96 + uu];
                float ig = sigf(zi);
                float fg = sigf(zf);
                float gg = tanhf_fast(zg);
                float og = sigf(zo);
                float cc = fg * cs[uu * 17 + bi] + ig * gg;
                cs[uu * 17 + bi] = cc;
                float hh = og * tanhf_fast(cc);
                hnext[(b0 + bi) * 256 + u0 + uu] = hh;
                outp[((b0 + bi) * 256 + t) * 256 + u0 + uu] = hh;
            }
        }
        group_barrier(grp, &s_sense);
    }
}

// ---------------------------------------------------------------------------
// Merge: out = 0.5 * (out2f + out1f + out2b + out1b)  (residual + average)
// ---------------------------------------------------------------------------
__global__ __launch_bounds__(256) void merge_kernel(float4* __restrict__ out) {
    int i = blockIdx.x * blockDim.x + threadIdx.x;
    const float4* a = (const float4*)g_out1[0];
    const float4* b = (const float4*)g_out2[0];
    const float4* c = (const float4*)g_out1[1];
    const float4* d = (const float4*)g_out2[1];
    float4 va = a[i], vb = b[i], vc = c[i], vd = d[i];
    float4 o;
    o.x = 0.5f * (va.x + vb.x + vc.x + vd.x);
    o.y = 0.5f * (va.y + vb.y + vc.y + vd.y);
    o.z = 0.5f * (va.z + vb.z + vc.z + vd.z);
    o.w = 0.5f * (va.w + vb.w + vc.w + vd.w);
    out[i] = o;
}

// ---------------------------------------------------------------------------
extern "C" void kernel_launch(void* const* d_in, const int* in_sizes, int n_in,
                              void* d_out, int out_size) {
    (void)in_sizes; (void)n_in; (void)out_size;
    const float* x   = (const float*)d_in[0];
    const float* kfw = (const float*)d_in[1];
    const float* rfw = (const float*)d_in[2];
    const float* bfw = (const float*)d_in[3];
    const float* kbw = (const float*)d_in[4];
    const float* rbw = (const float*)d_in[5];
    const float* bbw = (const float*)d_in[6];
    float* out = (float*)d_out;

    cudaFuncSetAttribute(rec_kernel,
                         cudaFuncAttributeMaxDynamicSharedMemorySize,
                         REC_SMEM_BYTES);

    dim3 gg(16, 256, 2);
    gemm_xz_kernel<<<gg, 256>>>(x, kfw, kbw, bfw, bbw, 0);
    rec_kernel<<<128, 128, REC_SMEM_BYTES>>>(rfw, rbw, 0);
    gemm_xz_kernel<<<gg, 256>>>(x, kfw, kbw, bfw, bbw, 1);
    rec_kernel<<<128, 128, REC_SMEM_BYTES>>>(rfw, rbw, 1);
    merge_kernel<<<8192, 256>>>((float4*)out);
}

// round 3
// speedup vs baseline: 1.3005x; 1.3005x over previous
#include <cuda_runtime.h>

// ---------------------------------------------------------------------------
// BiLSTM fp32. Round 3: FFMA2 reverted (regressed). Rec kernel reworked for
// latency hiding: 256 threads (2 warps/SMSP), broadcast-friendly layouts,
// pre-transposed h exchange through global.
// ---------------------------------------------------------------------------

#define B_DIM 128

// ---- scratch (device globals; allocation is forbidden) --------------------
__device__ float g_xz[2][33554432];     // [dir][(b*T+t)*1024 + col]
__device__ float g_out1[2][8388608];    // [dir][(b*T+t)*256 + u]
__device__ float g_out2[2][8388608];
__device__ float g_hT[2][2][8][4096];   // [dir][phase][batch_tile][k*16 + row]
__device__ unsigned g_cnt[16];
__device__ volatile unsigned g_sns[16];

__device__ __forceinline__ float sigf(float x) {
    return 1.0f / (1.0f + __expf(-x));
}
__device__ __forceinline__ float tanhf_fast(float x) {
    return 2.0f / (1.0f + __expf(-2.0f * x)) - 1.0f;
}

// ---------------------------------------------------------------------------
// GEMM: C[M=32768, N=1024] = A[M,256] @ W[256,1024] + bias   (round-1 version)
// BM=128, BN=64, BK=16, 256 threads, 8x4 per thread. grid=(16,256,2).
// ---------------------------------------------------------------------------
__global__ __launch_bounds__(256) void gemm_xz_kernel(
    const float* __restrict__ x,
    const float* __restrict__ kfw, const float* __restrict__ kbw,
    const float* __restrict__ bfw, const float* __restrict__ bbw,
    int layer)
{
    const int dir = blockIdx.z;
    const float* __restrict__ A = (layer == 0) ? x : g_out1[dir];
    const float* __restrict__ W = (dir ? kbw : kfw) + layer * 262144;
    const float* __restrict__ bias = (dir ? bbw : bfw) + layer * 1024;
    float* __restrict__ C = g_xz[dir];

    const int m0 = blockIdx.y * 128;
    const int n0 = blockIdx.x * 64;

    __shared__ float As[16][132];
    __shared__ float Bs[16][68];

    const int tid = threadIdx.x;
    const int tx = tid & 15;
    const int ty = tid >> 4;
    const int ar = tid >> 2;
    const int ac = (tid & 3) << 2;
    const int br = tid >> 4;
    const int bc = (tid & 15) << 2;

    float acc[8][4];
#pragma unroll
    for (int i = 0; i < 8; i++)
#pragma unroll
        for (int j = 0; j < 4; j++) acc[i][j] = 0.0f;

    for (int k0 = 0; k0 < 256; k0 += 16) {
        float4 a0 = *(const float4*)&A[(m0 + ar) * 256 + k0 + ac];
        float4 a1 = *(const float4*)&A[(m0 + ar + 64) * 256 + k0 + ac];
        float4 b0 = *(const float4*)&W[(k0 + br) * 1024 + n0 + bc];
        __syncthreads();
        As[ac + 0][ar] = a0.x; As[ac + 1][ar] = a0.y;
        As[ac + 2][ar] = a0.z; As[ac + 3][ar] = a0.w;
        As[ac + 0][ar + 64] = a1.x; As[ac + 1][ar + 64] = a1.y;
        As[ac + 2][ar + 64] = a1.z; As[ac + 3][ar + 64] = a1.w;
        *(float4*)&Bs[br][bc] = b0;
        __syncthreads();
#pragma unroll
        for (int kk = 0; kk < 16; kk++) {
            float4 aa0 = *(const float4*)&As[kk][ty * 8];
            float4 aa1 = *(const float4*)&As[kk][ty * 8 + 4];
            float4 bb  = *(const float4*)&Bs[kk][tx * 4];
            float a[8] = {aa0.x, aa0.y, aa0.z, aa0.w, aa1.x, aa1.y, aa1.z, aa1.w};
            float b[4] = {bb.x, bb.y, bb.z, bb.w};
#pragma unroll
            for (int i = 0; i < 8; i++)
#pragma unroll
                for (int j = 0; j < 4; j++) acc[i][j] += a[i] * b[j];
        }
    }

    float4 bv = *(const float4*)&bias[n0 + tx * 4];
#pragma unroll
    for (int i = 0; i < 8; i++) {
        float4 o;
        o.x = acc[i][0] + bv.x; o.y = acc[i][1] + bv.y;
        o.z = acc[i][2] + bv.z; o.w = acc[i][3] + bv.w;
        *(float4*)&C[(m0 + ty * 8 + i) * 1024 + n0 + tx * 4] = o;
    }
}

// ---------------------------------------------------------------------------
// Persistent recurrence kernel, 256 threads (8 warps).
// 128 CTAs = 2 dirs x 8 batch-tiles(16 rows) x 8 unit-tiles(32 units x 4 gates)
// Warp w: rows 4*(w&3)..+3, cols (w>>2)*64 + 2*lane (+1). Thread: 4 rows x 2
// cols. Inner loop per k per warp: 1 broadcast LDS.128 (h quad) + 1 LDS.64 (R
// pair) + 8 FFMA. h exchanged through global pre-transposed ([k][row]) so
// staging is fully coalesced and conflict-free.
// ---------------------------------------------------------------------------
#define REC_SMEM_FLOATS (32768 + 4096 + 2112 + 544 + 544)
#define REC_SMEM_BYTES (REC_SMEM_FLOATS * 4)

__device__ __forceinline__ void group_barrier(int grp, unsigned* s_sense) {
    __syncthreads();
    if (threadIdx.x == 0) {
        unsigned ls = *s_sense ^ 1u;
        *s_sense = ls;
        __threadfence();
        unsigned v = atomicAdd(&g_cnt[grp], 1u);
        if (v == 7u) {
            g_cnt[grp] = 0u;
            __threadfence();
            g_sns[grp] = ls;
        } else {
            while (g_sns[grp] != ls) { }
        }
    }
    __syncthreads();
}

__global__ __launch_bounds__(256) void rec_kernel(
    const float* __restrict__ rfw, const float* __restrict__ rbw, int layer)
{
    extern __shared__ float sm[];
    float* Rs    = sm;               // [256][128]  permuted (gate-block) cols
    float* hs    = Rs + 32768;       // [256][16]   h transposed (k-major)
    float* zs2   = hs + 4096;        // [16][132]   z exchange, row-major
    float* cs    = zs2 + 2112;       // [32][17]    cell state
    float* hsout = cs + 544;         // [32][17]    h staging for coalesced STG

    const int bx  = blockIdx.x;
    const int dir = bx >> 6;
    const int gt  = bx & 7;
    const int grp = bx >> 3;            // dir*8 + batch_tile
    const int bt  = (bx >> 3) & 7;
    const int b0  = bt * 16;
    const int u0  = gt * 32;

    const float* __restrict__ R   = (dir ? rbw : rfw) + layer * 262144;
    const float* __restrict__ xz  = g_xz[dir];
    float* __restrict__ outp      = layer ? g_out2[dir] : g_out1[dir];

    const int tid  = threadIdx.x;
    const int lane = tid & 31;
    const int w    = tid >> 5;

    __shared__ unsigned s_sense;
    if (tid == 0) s_sense = g_sns[grp];

    // Load R slice, permuted: tile col ci = q*32+uu <- original col q*256+u0+uu
    for (int idx = tid; idx < 256 * 128; idx += 256) {
        int k  = idx >> 7;
        int ci = idx & 127;
        int q  = ci >> 5;
        int uu = ci & 31;
        Rs[idx] = R[k * 1024 + q * 256 + u0 + uu];
    }

    // Init c = 0 and hT phase0 = 0 (this CTA's u-slice)
    for (int i = tid; i < 32 * 17; i += 256) cs[i] = 0.0f;
    {
        float* h0 = g_hT[dir][0][bt];
        for (int i = tid; i < 512; i += 256)
            h0[(u0 + (i >> 4)) * 16 + (i & 15)] = 0.0f;
    }
    group_barrier(grp, &s_sense);

    // compute-phase thread coordinates
    const int r0   = (w & 3) * 4;                 // row base
    const int ci0  = (w >> 2) * 64 + lane * 2;    // tile col base (even)
    const int q    = ci0 >> 5;
    const int uu0  = ci0 & 31;
    const int gcol = q * 256 + u0 + uu0;          // global xz col base

    // gate-phase thread coordinates
    const int guu = tid & 31;
    const int gb0 = (tid >> 5) * 2;

    for (int s = 0; s < 256; s++) {
        const int t = dir ? (255 - s) : s;
        const float* __restrict__ hTsrc = g_hT[dir][s & 1][bt];
        float* __restrict__ hTdst = g_hT[dir][(s & 1) ^ 1][bt];

        // Prefetch xz into accumulators (independent of h)
        float acc[4][2];
#pragma unroll
        for (int r = 0; r < 4; r++) {
            float2 v = *(const float2*)&xz[((b0 + r0 + r) * 256 + t) * 1024 + gcol];
            acc[r][0] = v.x; acc[r][1] = v.y;
        }

        // Stage h tile (already [k][row] in global): coalesced L2 loads
        {
            const float4* src = (const float4*)hTsrc + tid * 4;
            float4* dst = (float4*)hs + tid * 4;
#pragma unroll
            for (int j = 0; j < 4; j++) dst[j] = __ldcg(src + j);
        }
        __syncthreads();

        // z += h @ R_slice   (16 rows x 128 cols x 256 k)
#pragma unroll 8
        for (int k = 0; k < 256; k++) {
            float4 h4 = *(const float4*)&hs[k * 16 + r0];      // broadcast
            float2 r2 = *(const float2*)&Rs[k * 128 + ci0];
            acc[0][0] += h4.x * r2.x; acc[0][1] += h4.x * r2.y;
            acc[1][0] += h4.y * r2.x; acc[1][1] += h4.y * r2.y;
            acc[2][0] += h4.z * r2.x; acc[2][1] += h4.z * r2.y;
            acc[3][0] += h4.w * r2.x; acc[3][1] += h4.w * r2.y;
        }

        // Stash z to SMEM for gate regrouping
#pragma unroll
        for (int r = 0; r < 4; r++)
            *(float2*)&zs2[(r0 + r) * 132 + ci0] = make_float2(acc[r][0], acc[r][1]);
        __syncthreads();

        // Gate nonlinearities + state update: thread owns (unit guu, 2 rows)
#pragma unroll
        for (int j = 0; j < 2; j++) {
            int bi = gb0 + j;
            float zi = zs2[bi * 132 + guu];
            float zf = zs2[bi * 132 + 32 + guu];
            float zg = zs2[bi * 132 + 64 + guu];
            float zo = zs2[bi * 132 + 96 + guu];
            float ig = sigf(zi);
            float fg = sigf(zf);
            float gg = tanhf_fast(zg);
            float og = sigf(zo);
            float cc = fg * cs[guu * 17 + bi] + ig * gg;
            cs[guu * 17 + bi] = cc;
            float hh = og * tanhf_fast(cc);
            hsout[guu * 17 + bi] = hh;
            outp[((b0 + bi) * 256 + t) * 256 + u0 + guu] = hh;
        }
        __syncthreads();

        // Coalesced transposed h write-out: hTdst[(u0+ul)*16 + bi]
#pragma unroll
        for (int m = 0; m < 2; m++) {
            int ul = (tid >> 4) + 16 * m;
            int bi = tid & 15;
            hTdst[(u0 + ul) * 16 + bi] = hsout[ul * 17 + bi];
        }
        group_barrier(grp, &s_sense);
    }
}

// ---------------------------------------------------------------------------
// Merge: out = 0.5 * (out2f + out1f + out2b + out1b)  (residual + average)
// ---------------------------------------------------------------------------
__global__ __launch_bounds__(256) void merge_kernel(float4* __restrict__ out) {
    int i = blockIdx.x * blockDim.x + threadIdx.x;
    const float4* a = (const float4*)g_out1[0];
    const float4* b = (const float4*)g_out2[0];
    const float4* c = (const float4*)g_out1[1];
    const float4* d = (const float4*)g_out2[1];
    float4 va = a[i], vb = b[i], vc = c[i], vd = d[i];
    float4 o;
    o.x = 0.5f * (va.x + vb.x + vc.x + vd.x);
    o.y = 0.5f * (va.y + vb.y + vc.y + vd.y);
    o.z = 0.5f * (va.z + vb.z + vc.z + vd.z);
    o.w = 0.5f * (va.w + vb.w + vc.w + vd.w);
    out[i] = o;
}

// ---------------------------------------------------------------------------
extern "C" void kernel_launch(void* const* d_in, const int* in_sizes, int n_in,
                              void* d_out, int out_size) {
    (void)in_sizes; (void)n_in; (void)out_size;
    const float* x   = (const float*)d_in[0];
    const float* kfw = (const float*)d_in[1];
    const float* rfw = (const float*)d_in[2];
    const float* bfw = (const float*)d_in[3];
    const float* kbw = (const float*)d_in[4];
    const float* rbw = (const float*)d_in[5];
    const float* bbw = (const float*)d_in[6];
    float* out = (float*)d_out;

    cudaFuncSetAttribute(rec_kernel,
                         cudaFuncAttributeMaxDynamicSharedMemorySize,
                         REC_SMEM_BYTES);

    dim3 gg(16, 256, 2);
    gemm_xz_kernel<<<gg, 256>>>(x, kfw, kbw, bfw, bbw, 0);
    rec_kernel<<<128, 256, REC_SMEM_BYTES>>>(rfw, rbw, 0);
    gemm_xz_kernel<<<gg, 256>>>(x, kfw, kbw, bfw, bbw, 1);
    rec_kernel<<<128, 256, REC_SMEM_BYTES>>>(rfw, rbw, 1);
    merge_kernel<<<8192, 256>>>((float4*)out);
}

// round 4
// speedup vs baseline: 1.4311x; 1.1004x over previous
#include <cuda_runtime.h>

// ---------------------------------------------------------------------------
// BiLSTM fp32. Round 4: rec k-loop software-pipelined (explicit register
// double-buffer), one less sync per step; GEMM re-tiled to 128x128x8.
// ---------------------------------------------------------------------------

#define B_DIM 128

// ---- scratch (device globals; allocation is forbidden) --------------------
__device__ float g_xz[2][33554432];     // [dir][(b*T+t)*1024 + col]
__device__ float g_out1[2][8388608];    // [dir][(b*T+t)*256 + u]
__device__ float g_out2[2][8388608];
__device__ float g_hT[2][2][8][4096];   // [dir][phase][batch_tile][k*16 + row]
__device__ unsigned g_cnt[16];
__device__ volatile unsigned g_sns[16];

__device__ __forceinline__ float sigf(float x) {
    return 1.0f / (1.0f + __expf(-x));
}
__device__ __forceinline__ float tanhf_fast(float x) {
    return 2.0f / (1.0f + __expf(-2.0f * x)) - 1.0f;
}

// ---------------------------------------------------------------------------
// GEMM: C[M=32768, N=1024] = A[M,256] @ W[256,1024] + bias
// BM=128, BN=128, BK=8, 256 threads, 8x8 per thread. grid=(8,256,2).
// ---------------------------------------------------------------------------
__global__ __launch_bounds__(256, 2) void gemm_xz_kernel(
    const float* __restrict__ x,
    const float* __restrict__ kfw, const float* __restrict__ kbw,
    const float* __restrict__ bfw, const float* __restrict__ bbw,
    int layer)
{
    const int dir = blockIdx.z;
    const float* __restrict__ A = (layer == 0) ? x : g_out1[dir];
    const float* __restrict__ W = (dir ? kbw : kfw) + layer * 262144;
    const float* __restrict__ bias = (dir ? bbw : bfw) + layer * 1024;
    float* __restrict__ C = g_xz[dir];

    const int m0 = blockIdx.y * 128;
    const int n0 = blockIdx.x * 128;

    __shared__ float As[8][132];
    __shared__ float Bs[8][132];

    const int tid = threadIdx.x;
    const int tx = tid & 15;          // col group: 8*tx..8*tx+7
    const int ty = tid >> 4;          // row group: 8*ty..8*ty+7
    const int ar = tid >> 1;          // A load row (0..127)
    const int ac = (tid & 1) << 2;    // A load col (0,4)
    const int br = tid >> 5;          // B load row (0..7)
    const int bc = (tid & 31) << 2;   // B load col

    float acc[8][8];
#pragma unroll
    for (int i = 0; i < 8; i++)
#pragma unroll
        for (int j = 0; j < 8; j++) acc[i][j] = 0.0f;

    for (int k0 = 0; k0 < 256; k0 += 8) {
        float4 a0 = *(const float4*)&A[(m0 + ar) * 256 + k0 + ac];
        float4 b0 = *(const float4*)&W[(k0 + br) * 1024 + n0 + bc];
        __syncthreads();
        As[ac + 0][ar] = a0.x; As[ac + 1][ar] = a0.y;
        As[ac + 2][ar] = a0.z; As[ac + 3][ar] = a0.w;
        *(float4*)&Bs[br][bc] = b0;
        __syncthreads();
#pragma unroll
        for (int kk = 0; kk < 8; kk++) {
            float4 aa0 = *(const float4*)&As[kk][ty * 8];
            float4 aa1 = *(const float4*)&As[kk][ty * 8 + 4];
            float4 bb0 = *(const float4*)&Bs[kk][tx * 8];
            float4 bb1 = *(const float4*)&Bs[kk][tx * 8 + 4];
            float a[8] = {aa0.x, aa0.y, aa0.z, aa0.w, aa1.x, aa1.y, aa1.z, aa1.w};
            float b[8] = {bb0.x, bb0.y, bb0.z, bb0.w, bb1.x, bb1.y, bb1.z, bb1.w};
#pragma unroll
            for (int i = 0; i < 8; i++)
#pragma unroll
                for (int j = 0; j < 8; j++) acc[i][j] += a[i] * b[j];
        }
    }

    float4 bv0 = *(const float4*)&bias[n0 + tx * 8];
    float4 bv1 = *(const float4*)&bias[n0 + tx * 8 + 4];
    float bb[8] = {bv0.x, bv0.y, bv0.z, bv0.w, bv1.x, bv1.y, bv1.z, bv1.w};
#pragma unroll
    for (int i = 0; i < 8; i++) {
        float4 o0, o1;
        o0.x = acc[i][0] + bb[0]; o0.y = acc[i][1] + bb[1];
        o0.z = acc[i][2] + bb[2]; o0.w = acc[i][3] + bb[3];
        o1.x = acc[i][4] + bb[4]; o1.y = acc[i][5] + bb[5];
        o1.z = acc[i][6] + bb[6]; o1.w = acc[i][7] + bb[7];
        *(float4*)&C[(m0 + ty * 8 + i) * 1024 + n0 + tx * 8] = o0;
        *(float4*)&C[(m0 + ty * 8 + i) * 1024 + n0 + tx * 8 + 4] = o1;
    }
}

// ---------------------------------------------------------------------------
// Persistent recurrence kernel, 256 threads (8 warps).
// 128 CTAs = 2 dirs x 8 batch-tiles(16 rows) x 8 unit-tiles(32 units x 4 gates)
// Warp w: rows 4*(w&3), cols (w>>2)*64 + 2*lane. Thread: 4 rows x 2 cols.
// k-loop software-pipelined: registers hold (h,R) for k while (k+1) loads.
// ---------------------------------------------------------------------------
#define REC_SMEM_FLOATS (32768 + 4096 + 2112 + 544)
#define REC_SMEM_BYTES (REC_SMEM_FLOATS * 4)

__device__ __forceinline__ void group_barrier(int grp, unsigned* s_sense) {
    __syncthreads();
    if (threadIdx.x == 0) {
        unsigned ls = *s_sense ^ 1u;
        *s_sense = ls;
        __threadfence();
        unsigned v = atomicAdd(&g_cnt[grp], 1u);
        if (v == 7u) {
            g_cnt[grp] = 0u;
            __threadfence();
            g_sns[grp] = ls;
        } else {
            while (g_sns[grp] != ls) { }
        }
    }
    __syncthreads();
}

__global__ __launch_bounds__(256, 1) void rec_kernel(
    const float* __restrict__ rfw, const float* __restrict__ rbw, int layer)
{
    extern __shared__ float sm[];
    float* Rs    = sm;               // [256][128]  permuted (gate-block) cols
    float* hs    = Rs + 32768;       // [256][16]   h transposed (k-major)
    float* zs2   = hs + 4096;        // [16][132]   z exchange, row-major
    float* cs    = zs2 + 2112;       // [32][17]    cell state

    const int bx  = blockIdx.x;
    const int dir = bx >> 6;
    const int gt  = bx & 7;
    const int grp = bx >> 3;            // dir*8 + batch_tile
    const int bt  = (bx >> 3) & 7;
    const int b0  = bt * 16;
    const int u0  = gt * 32;

    const float* __restrict__ R   = (dir ? rbw : rfw) + layer * 262144;
    const float* __restrict__ xz  = g_xz[dir];
    float* __restrict__ outp      = layer ? g_out2[dir] : g_out1[dir];

    const int tid  = threadIdx.x;
    const int lane = tid & 31;
    const int w    = tid >> 5;

    __shared__ unsigned s_sense;
    if (tid == 0) s_sense = g_sns[grp];

    // Load R slice, permuted: tile col ci = q*32+uu <- original col q*256+u0+uu
    for (int idx = tid; idx < 256 * 128; idx += 256) {
        int k  = idx >> 7;
        int ci = idx & 127;
        int q  = ci >> 5;
        int uu = ci & 31;
        Rs[idx] = R[k * 1024 + q * 256 + u0 + uu];
    }

    // Init c = 0 and hT phase0 = 0 (this CTA's u-slice)
    for (int i = tid; i < 32 * 17; i += 256) cs[i] = 0.0f;
    {
        float* h0 = g_hT[dir][0][bt];
        for (int i = tid; i < 512; i += 256)
            h0[(u0 + (i >> 4)) * 16 + (i & 15)] = 0.0f;
    }
    group_barrier(grp, &s_sense);

    // compute-phase thread coordinates
    const int r0   = (w & 3) * 4;                 // row base
    const int ci0  = (w >> 2) * 64 + lane * 2;    // tile col base (even)
    const int q    = ci0 >> 5;
    const int uu0  = ci0 & 31;
    const int gcol = q * 256 + u0 + uu0;          // global xz col base

    // gate-phase thread coordinates
    const int guu = tid & 31;
    const int gb0 = (tid >> 5) * 2;

    for (int s = 0; s < 256; s++) {
        const int t = dir ? (255 - s) : s;
        const float* __restrict__ hTsrc = g_hT[dir][s & 1][bt];
        float* __restrict__ hTdst = g_hT[dir][(s & 1) ^ 1][bt];

        // Prefetch xz into accumulators (independent of h)
        float acc[4][2];
#pragma unroll
        for (int r = 0; r < 4; r++) {
            float2 v = *(const float2*)&xz[((b0 + r0 + r) * 256 + t) * 1024 + gcol];
            acc[r][0] = v.x; acc[r][1] = v.y;
        }

        // Stage h tile (already [k][row] in global): coalesced L2 loads
        {
            const float4* src = (const float4*)hTsrc + tid * 4;
            float4* dst = (float4*)hs + tid * 4;
#pragma unroll
            for (int j = 0; j < 4; j++) dst[j] = __ldcg(src + j);
        }
        __syncthreads();

        // z += h @ R_slice  (software-pipelined: prefetch k+1 while FMA on k)
        {
            float4 hq = *(const float4*)&hs[r0];
            float2 rq = *(const float2*)&Rs[ci0];
#pragma unroll 8
            for (int k = 0; k < 255; k++) {
                float4 hn = *(const float4*)&hs[(k + 1) * 16 + r0];
                float2 rn = *(const float2*)&Rs[(k + 1) * 128 + ci0];
                acc[0][0] += hq.x * rq.x; acc[0][1] += hq.x * rq.y;
                acc[1][0] += hq.y * rq.x; acc[1][1] += hq.y * rq.y;
                acc[2][0] += hq.z * rq.x; acc[2][1] += hq.z * rq.y;
                acc[3][0] += hq.w * rq.x; acc[3][1] += hq.w * rq.y;
                hq = hn; rq = rn;
            }
            acc[0][0] += hq.x * rq.x; acc[0][1] += hq.x * rq.y;
            acc[1][0] += hq.y * rq.x; acc[1][1] += hq.y * rq.y;
            acc[2][0] += hq.z * rq.x; acc[2][1] += hq.z * rq.y;
            acc[3][0] += hq.w * rq.x; acc[3][1] += hq.w * rq.y;
        }

        // Stash z to SMEM for gate regrouping
#pragma unroll
        for (int r = 0; r < 4; r++)
            *(float2*)&zs2[(r0 + r) * 132 + ci0] = make_float2(acc[r][0], acc[r][1]);
        __syncthreads();

        // Gate nonlinearities + state update: thread owns (unit guu, 2 rows).
        // Writes h directly to transposed global buffer (no smem staging).
        float hh2[2];
#pragma unroll
        for (int j = 0; j < 2; j++) {
            int bi = gb0 + j;
            float zi = zs2[bi * 132 + guu];
            float zf = zs2[bi * 132 + 32 + guu];
            float zg = zs2[bi * 132 + 64 + guu];
            float zo = zs2[bi * 132 + 96 + guu];
            float ig = sigf(zi);
            float fg = sigf(zf);
            float gg = tanhf_fast(zg);
            float og = sigf(zo);
            float cc = fg * cs[guu * 17 + bi] + ig * gg;
            cs[guu * 17 + bi] = cc;
            float hh = og * tanhf_fast(cc);
            hh2[j] = hh;
            outp[((b0 + bi) * 256 + t) * 256 + u0 + guu] = hh;
        }
        *(float2*)&hTdst[(u0 + guu) * 16 + gb0] = make_float2(hh2[0], hh2[1]);

        group_barrier(grp, &s_sense);
    }
}

// ---------------------------------------------------------------------------
// Merge: out = 0.5 * (out2f + out1f + out2b + out1b)  (residual + average)
// ---------------------------------------------------------------------------
__global__ __launch_bounds__(256) void merge_kernel(float4* __restrict__ out) {
    int i = blockIdx.x * blockDim.x + threadIdx.x;
    const float4* a = (const float4*)g_out1[0];
    const float4* b = (const float4*)g_out2[0];
    const float4* c = (const float4*)g_out1[1];
    const float4* d = (const float4*)g_out2[1];
    float4 va = a[i], vb = b[i], vc = c[i], vd = d[i];
    float4 o;
    o.x = 0.5f * (va.x + vb.x + vc.x + vd.x);
    o.y = 0.5f * (va.y + vb.y + vc.y + vd.y);
    o.z = 0.5f * (va.z + vb.z + vc.z + vd.z);
    o.w = 0.5f * (va.w + vb.w + vc.w + vd.w);
    out[i] = o;
}

// ---------------------------------------------------------------------------
extern "C" void kernel_launch(void* const* d_in, const int* in_sizes, int n_in,
                              void* d_out, int out_size) {
    (void)in_sizes; (void)n_in; (void)out_size;
    const float* x   = (const float*)d_in[0];
    const float* kfw = (const float*)d_in[1];
    const float* rfw = (const float*)d_in[2];
    const float* bfw = (const float*)d_in[3];
    const float* kbw = (const float*)d_in[4];
    const float* rbw = (const float*)d_in[5];
    const float* bbw = (const float*)d_in[6];
    float* out = (float*)d_out;

    cudaFuncSetAttribute(rec_kernel,
                         cudaFuncAttributeMaxDynamicSharedMemorySize,
                         REC_SMEM_BYTES);

    dim3 gg(8, 256, 2);
    gemm_xz_kernel<<<gg, 256>>>(x, kfw, kbw, bfw, bbw, 0);
    rec_kernel<<<128, 256, REC_SMEM_BYTES>>>(rfw, rbw, 0);
    gemm_xz_kernel<<<gg, 256>>>(x, kfw, kbw, bfw, bbw, 1);
    rec_kernel<<<128, 256, REC_SMEM_BYTES>>>(rfw, rbw, 1);
    merge_kernel<<<8192, 256>>>((float4*)out);
}

// round 5
// speedup vs baseline: 1.4900x; 1.0412x over previous
#include <cuda_runtime.h>

// ---------------------------------------------------------------------------
// BiLSTM fp32. Round 5: rec kernel moves to 512 threads (4 warps/SMSP) with
// split-K (two K-halves, SMEM reduction) for latency hiding near the fp32
// FFMA floor. GEMM/merge unchanged from round 4.
// ---------------------------------------------------------------------------

#define B_DIM 128

// ---- scratch (device globals; allocation is forbidden) --------------------
__device__ float g_xz[2][33554432];     // [dir][(b*T+t)*1024 + col]
__device__ float g_out1[2][8388608];    // [dir][(b*T+t)*256 + u]
__device__ float g_out2[2][8388608];
__device__ float g_hT[2][2][8][4096];   // [dir][phase][batch_tile][k*16 + row]
__device__ unsigned g_cnt[16];
__device__ volatile unsigned g_sns[16];

__device__ __forceinline__ float sigf(float x) {
    return 1.0f / (1.0f + __expf(-x));
}
__device__ __forceinline__ float tanhf_fast(float x) {
    return 2.0f / (1.0f + __expf(-2.0f * x)) - 1.0f;
}

// ---------------------------------------------------------------------------
// GEMM: C[M=32768, N=1024] = A[M,256] @ W[256,1024] + bias
// BM=128, BN=128, BK=8, 256 threads, 8x8 per thread. grid=(8,256,2).
// ---------------------------------------------------------------------------
__global__ __launch_bounds__(256, 2) void gemm_xz_kernel(
    const float* __restrict__ x,
    const float* __restrict__ kfw, const float* __restrict__ kbw,
    const float* __restrict__ bfw, const float* __restrict__ bbw,
    int layer)
{
    const int dir = blockIdx.z;
    const float* __restrict__ A = (layer == 0) ? x : g_out1[dir];
    const float* __restrict__ W = (dir ? kbw : kfw) + layer * 262144;
    const float* __restrict__ bias = (dir ? bbw : bfw) + layer * 1024;
    float* __restrict__ C = g_xz[dir];

    const int m0 = blockIdx.y * 128;
    const int n0 = blockIdx.x * 128;

    __shared__ float As[8][132];
    __shared__ float Bs[8][132];

    const int tid = threadIdx.x;
    const int tx = tid & 15;
    const int ty = tid >> 4;
    const int ar = tid >> 1;
    const int ac = (tid & 1) << 2;
    const int br = tid >> 5;
    const int bc = (tid & 31) << 2;

    float acc[8][8];
#pragma unroll
    for (int i = 0; i < 8; i++)
#pragma unroll
        for (int j = 0; j < 8; j++) acc[i][j] = 0.0f;

    for (int k0 = 0; k0 < 256; k0 += 8) {
        float4 a0 = *(const float4*)&A[(m0 + ar) * 256 + k0 + ac];
        float4 b0 = *(const float4*)&W[(k0 + br) * 1024 + n0 + bc];
        __syncthreads();
        As[ac + 0][ar] = a0.x; As[ac + 1][ar] = a0.y;
        As[ac + 2][ar] = a0.z; As[ac + 3][ar] = a0.w;
        *(float4*)&Bs[br][bc] = b0;
        __syncthreads();
#pragma unroll
        for (int kk = 0; kk < 8; kk++) {
            float4 aa0 = *(const float4*)&As[kk][ty * 8];
            float4 aa1 = *(const float4*)&As[kk][ty * 8 + 4];
            float4 bb0 = *(const float4*)&Bs[kk][tx * 8];
            float4 bb1 = *(const float4*)&Bs[kk][tx * 8 + 4];
            float a[8] = {aa0.x, aa0.y, aa0.z, aa0.w, aa1.x, aa1.y, aa1.z, aa1.w};
            float b[8] = {bb0.x, bb0.y, bb0.z, bb0.w, bb1.x, bb1.y, bb1.z, bb1.w};
#pragma unroll
            for (int i = 0; i < 8; i++)
#pragma unroll
                for (int j = 0; j < 8; j++) acc[i][j] += a[i] * b[j];
        }
    }

    float4 bv0 = *(const float4*)&bias[n0 + tx * 8];
    float4 bv1 = *(const float4*)&bias[n0 + tx * 8 + 4];
    float bb[8] = {bv0.x, bv0.y, bv0.z, bv0.w, bv1.x, bv1.y, bv1.z, bv1.w};
#pragma unroll
    for (int i = 0; i < 8; i++) {
        float4 o0, o1;
        o0.x = acc[i][0] + bb[0]; o0.y = acc[i][1] + bb[1];
        o0.z = acc[i][2] + bb[2]; o0.w = acc[i][3] + bb[3];
        o1.x = acc[i][4] + bb[4]; o1.y = acc[i][5] + bb[5];
        o1.z = acc[i][6] + bb[6]; o1.w = acc[i][7] + bb[7];
        *(float4*)&C[(m0 + ty * 8 + i) * 1024 + n0 + tx * 8] = o0;
        *(float4*)&C[(m0 + ty * 8 + i) * 1024 + n0 + tx * 8 + 4] = o1;
    }
}

// ---------------------------------------------------------------------------
// Persistent recurrence kernel, 512 threads (16 warps, 4/SMSP).
// 128 CTAs = 2 dirs x 8 batch-tiles(16 rows) x 8 unit-tiles(32 units x 4 gates)
// Warp w: rows 4*(w&3), col-half (w>>2)&1 (64 cols, thread 4x2), K-half w>>3.
// Partial z per K-half goes to its SMEM plane; gate phase sums both planes.
// ---------------------------------------------------------------------------
#define REC_SMEM_FLOATS (32768 + 4096 + 2 * 2112 + 544)
#define REC_SMEM_BYTES (REC_SMEM_FLOATS * 4)

__device__ __forceinline__ void group_barrier(int grp, unsigned* s_sense) {
    __syncthreads();
    if (threadIdx.x == 0) {
        unsigned ls = *s_sense ^ 1u;
        *s_sense = ls;
        __threadfence();
        unsigned v = atomicAdd(&g_cnt[grp], 1u);
        if (v == 7u) {
            g_cnt[grp] = 0u;
            __threadfence();
            g_sns[grp] = ls;
        } else {
            while (g_sns[grp] != ls) { }
        }
    }
    __syncthreads();
}

__global__ __launch_bounds__(512, 1) void rec_kernel(
    const float* __restrict__ rfw, const float* __restrict__ rbw, int layer)
{
    extern __shared__ float sm[];
    float* Rs    = sm;               // [256][128]  permuted (gate-block) cols
    float* hs    = Rs + 32768;       // [256][16]   h transposed (k-major)
    float* zs2   = hs + 4096;        // [2][16][132] z partials per K-half
    float* cs    = zs2 + 2 * 2112;   // [32][17]    cell state

    const int bx  = blockIdx.x;
    const int dir = bx >> 6;
    const int gt  = bx & 7;
    const int grp = bx >> 3;            // dir*8 + batch_tile
    const int bt  = (bx >> 3) & 7;
    const int b0  = bt * 16;
    const int u0  = gt * 32;

    const float* __restrict__ R   = (dir ? rbw : rfw) + layer * 262144;
    const float* __restrict__ xz  = g_xz[dir];
    float* __restrict__ outp      = layer ? g_out2[dir] : g_out1[dir];

    const int tid  = threadIdx.x;
    const int lane = tid & 31;
    const int w    = tid >> 5;

    __shared__ unsigned s_sense;
    if (tid == 0) s_sense = g_sns[grp];

    // Load R slice, permuted: tile col ci = q*32+uu <- original col q*256+u0+uu
    for (int idx = tid; idx < 256 * 128; idx += 512) {
        int k  = idx >> 7;
        int ci = idx & 127;
        int q  = ci >> 5;
        int uu = ci & 31;
        Rs[idx] = R[k * 1024 + q * 256 + u0 + uu];
    }

    // Init c = 0 and hT phase0 = 0 (this CTA's u-slice)
    for (int i = tid; i < 32 * 17; i += 512) cs[i] = 0.0f;
    if (tid < 512) {
        float* h0 = g_hT[dir][0][bt];
        h0[(u0 + (tid >> 4)) * 16 + (tid & 15)] = 0.0f;
    }
    group_barrier(grp, &s_sense);

    // compute-phase thread coordinates
    const int r0   = (w & 3) * 4;                     // row base
    const int ch   = (w >> 2) & 1;                    // col half
    const int kh   = w >> 3;                          // K half
    const int k0   = kh * 128;
    const int ci0  = ch * 64 + lane * 2;              // tile col base (even)
    const int q    = ci0 >> 5;
    const int uu0  = ci0 & 31;
    const int gcol = q * 256 + u0 + uu0;              // global xz col base
    float* zplane  = zs2 + kh * 2112;

    // gate-phase thread coordinates (512 threads: 1 row x 1 unit each)
    const int guu = tid & 31;
    const int gbi = tid >> 5;          // 0..15

    for (int s = 0; s < 256; s++) {
        const int t = dir ? (255 - s) : s;
        const float* __restrict__ hTsrc = g_hT[dir][s & 1][bt];
        float* __restrict__ hTdst = g_hT[dir][(s & 1) ^ 1][bt];

        // K-half 0 warps seed accumulators with xz; K-half 1 with 0
        float acc[4][2];
        if (kh == 0) {
#pragma unroll
            for (int r = 0; r < 4; r++) {
                float2 v = *(const float2*)&xz[((b0 + r0 + r) * 256 + t) * 1024 + gcol];
                acc[r][0] = v.x; acc[r][1] = v.y;
            }
        } else {
#pragma unroll
            for (int r = 0; r < 4; r++) { acc[r][0] = 0.0f; acc[r][1] = 0.0f; }
        }

        // Stage h tile (already [k][row] in global): coalesced L2 loads
        if (tid < 256) {
            const float4* src = (const float4*)hTsrc + tid * 4;
            float4* dst = (float4*)hs + tid * 4;
#pragma unroll
            for (int j = 0; j < 4; j++) dst[j] = __ldcg(src + j);
        }
        __syncthreads();

        // z_partial += h @ R_slice over this warp's K half (pipelined)
        {
            float4 hq = *(const float4*)&hs[k0 * 16 + r0];
            float2 rq = *(const float2*)&Rs[k0 * 128 + ci0];
#pragma unroll 8
            for (int k = k0; k < k0 + 127; k++) {
                float4 hn = *(const float4*)&hs[(k + 1) * 16 + r0];
                float2 rn = *(const float2*)&Rs[(k + 1) * 128 + ci0];
                acc[0][0] += hq.x * rq.x; acc[0][1] += hq.x * rq.y;
                acc[1][0] += hq.y * rq.x; acc[1][1] += hq.y * rq.y;
                acc[2][0] += hq.z * rq.x; acc[2][1] += hq.z * rq.y;
                acc[3][0] += hq.w * rq.x; acc[3][1] += hq.w * rq.y;
                hq = hn; rq = rn;
            }
            acc[0][0] += hq.x * rq.x; acc[0][1] += hq.x * rq.y;
            acc[1][0] += hq.y * rq.x; acc[1][1] += hq.y * rq.y;
            acc[2][0] += hq.z * rq.x; acc[2][1] += hq.z * rq.y;
            acc[3][0] += hq.w * rq.x; acc[3][1] += hq.w * rq.y;
        }

        // Stash z partials to this K-half's SMEM plane
#pragma unroll
        for (int r = 0; r < 4; r++)
            *(float2*)&zplane[(r0 + r) * 132 + ci0] = make_float2(acc[r][0], acc[r][1]);
        __syncthreads();

        // Gate nonlinearities + state update: thread owns (row gbi, unit guu)
        {
            float zi = zs2[gbi * 132 + guu]        + zs2[2112 + gbi * 132 + guu];
            float zf = zs2[gbi * 132 + 32 + guu]   + zs2[2112 + gbi * 132 + 32 + guu];
            float zg = zs2[gbi * 132 + 64 + guu]   + zs2[2112 + gbi * 132 + 64 + guu];
            float zo = zs2[gbi * 132 + 96 + guu]   + zs2[2112 + gbi * 132 + 96 + guu];
            float ig = sigf(zi);
            float fg = sigf(zf);
            float gg = tanhf_fast(zg);
            float og = sigf(zo);
            float cc = fg * cs[guu * 17 + gbi] + ig * gg;
            cs[guu * 17 + gbi] = cc;
            float hh = og * tanhf_fast(cc);
            outp[((b0 + gbi) * 256 + t) * 256 + u0 + guu] = hh;
            hTdst[(u0 + guu) * 16 + gbi] = hh;
        }

        group_barrier(grp, &s_sense);
    }
}

// ---------------------------------------------------------------------------
// Merge: out = 0.5 * (out2f + out1f + out2b + out1b)  (residual + average)
// ---------------------------------------------------------------------------
__global__ __launch_bounds__(256) void merge_kernel(float4* __restrict__ out) {
    int i = blockIdx.x * blockDim.x + threadIdx.x;
    const float4* a = (const float4*)g_out1[0];
    const float4* b = (const float4*)g_out2[0];
    const float4* c = (const float4*)g_out1[1];
    const float4* d = (const float4*)g_out2[1];
    float4 va = a[i], vb = b[i], vc = c[i], vd = d[i];
    float4 o;
    o.x = 0.5f * (va.x + vb.x + vc.x + vd.x);
    o.y = 0.5f * (va.y + vb.y + vc.y + vd.y);
    o.z = 0.5f * (va.z + vb.z + vc.z + vd.z);
    o.w = 0.5f * (va.w + vb.w + vc.w + vd.w);
    out[i] = o;
}

// ---------------------------------------------------------------------------
extern "C" void kernel_launch(void* const* d_in, const int* in_sizes, int n_in,
                              void* d_out, int out_size) {
    (void)in_sizes; (void)n_in; (void)out_size;
    const float* x   = (const float*)d_in[0];
    const float* kfw = (const float*)d_in[1];
    const float* rfw = (const float*)d_in[2];
    const float* bfw = (const float*)d_in[3];
    const float* kbw = (const float*)d_in[4];
    const float* rbw = (const float*)d_in[5];
    const float* bbw = (const float*)d_in[6];
    float* out = (float*)d_out;

    cudaFuncSetAttribute(rec_kernel,
                         cudaFuncAttributeMaxDynamicSharedMemorySize,
                         REC_SMEM_BYTES);

    dim3 gg(8, 256, 2);
    gemm_xz_kernel<<<gg, 256>>>(x, kfw, kbw, bfw, bbw, 0);
    rec_kernel<<<128, 512, REC_SMEM_BYTES>>>(rfw, rbw, 0);
    gemm_xz_kernel<<<gg, 256>>>(x, kfw, kbw, bfw, bbw, 1);
    rec_kernel<<<128, 512, REC_SMEM_BYTES>>>(rfw, rbw, 1);
    merge_kernel<<<8192, 256>>>((float4*)out);
}

// round 7
// speedup vs baseline: 1.7968x; 1.2059x over previous
#include <cuda_runtime.h>
#include <cuda_bf16.h>
#include <stdint.h>

// ---------------------------------------------------------------------------
// BiLSTM fp32. Round 7: recurrence on HMMA tensor cores via arch-portable
// mma.sync.m16n8k16.bf16 + ldmatrix (tcgen05 unavailable: harness compiles
// compute_103 without the 'a' feature). bf16 2-term split, 3 MMA terms ->
// fp32-grade accuracy. Persistent 128-CTA kernel, proven 8-CTA barrier.
// GEMM / merge unchanged (scalar fp32).
// ---------------------------------------------------------------------------

// ---- scratch (device globals; allocation is forbidden) --------------------
__device__ float g_xz[2][33554432];     // [dir][(b*T+t)*1024 + col]
__device__ float g_out1[2][8388608];    // [dir][(b*T+t)*256 + u]
__device__ float g_out2[2][8388608];
// h exchange: SMEM-image layout [16 rows][264 k] bf16, hi plane then lo plane
// (8448 B each, 16896 B total) per [dir][phase][batch_tile]
__device__ __align__(16) unsigned char g_himg[2][2][8][16896];
__device__ unsigned g_cnt[16];
__device__ volatile unsigned g_sns[16];

__device__ __forceinline__ float sigf(float x) {
    return 1.0f / (1.0f + __expf(-x));
}
__device__ __forceinline__ float tanhf_fast(float x) {
    return 2.0f / (1.0f + __expf(-2.0f * x)) - 1.0f;
}
__device__ __forceinline__ uint32_t smem_u32(const void* p) {
    uint32_t a;
    asm("{ .reg .u64 t; cvta.to.shared.u64 t, %1; cvt.u32.u64 %0, t; }"
        : "=r"(a) : "l"(p));
    return a;
}

#define LDSM4(r0, r1, r2, r3, addr) \
    asm volatile("ldmatrix.sync.aligned.m8n8.x4.shared.b16 {%0,%1,%2,%3}, [%4];" \
                 : "=r"(r0), "=r"(r1), "=r"(r2), "=r"(r3) : "r"(addr))

#define MMA16816(c0, c1, c2, c3, a0, a1, a2, a3, b0, b1) \
    asm volatile("mma.sync.aligned.m16n8k16.row.col.f32.bf16.bf16.f32 " \
                 "{%0,%1,%2,%3}, {%4,%5,%6,%7}, {%8,%9}, {%0,%1,%2,%3};" \
                 : "+f"(c0), "+f"(c1), "+f"(c2), "+f"(c3) \
                 : "r"(a0), "r"(a1), "r"(a2), "r"(a3), "r"(b0), "r"(b1))

// ---------------------------------------------------------------------------
// GEMM: C[M=32768, N=1024] = A[M,256] @ W[256,1024] + bias  (round-4 version)
// ---------------------------------------------------------------------------
__global__ __launch_bounds__(256, 2) void gemm_xz_kernel(
    const float* __restrict__ x,
    const float* __restrict__ kfw, const float* __restrict__ kbw,
    const float* __restrict__ bfw, const float* __restrict__ bbw,
    int layer)
{
    const int dir = blockIdx.z;
    const float* __restrict__ A = (layer == 0) ? x : g_out1[dir];
    const float* __restrict__ W = (dir ? kbw : kfw) + layer * 262144;
    const float* __restrict__ bias = (dir ? bbw : bfw) + layer * 1024;
    float* __restrict__ C = g_xz[dir];

    const int m0 = blockIdx.y * 128;
    const int n0 = blockIdx.x * 128;

    __shared__ float As[8][132];
    __shared__ float Bs[8][132];

    const int tid = threadIdx.x;
    const int tx = tid & 15;
    const int ty = tid >> 4;
    const int ar = tid >> 1;
    const int ac = (tid & 1) << 2;
    const int br = tid >> 5;
    const int bc = (tid & 31) << 2;

    float acc[8][8];
#pragma unroll
    for (int i = 0; i < 8; i++)
#pragma unroll
        for (int j = 0; j < 8; j++) acc[i][j] = 0.0f;

    for (int k0 = 0; k0 < 256; k0 += 8) {
        float4 a0 = *(const float4*)&A[(m0 + ar) * 256 + k0 + ac];
        float4 b0 = *(const float4*)&W[(k0 + br) * 1024 + n0 + bc];
        __syncthreads();
        As[ac + 0][ar] = a0.x; As[ac + 1][ar] = a0.y;
        As[ac + 2][ar] = a0.z; As[ac + 3][ar] = a0.w;
        *(float4*)&Bs[br][bc] = b0;
        __syncthreads();
#pragma unroll
        for (int kk = 0; kk < 8; kk++) {
            float4 aa0 = *(const float4*)&As[kk][ty * 8];
            float4 aa1 = *(const float4*)&As[kk][ty * 8 + 4];
            float4 bb0 = *(const float4*)&Bs[kk][tx * 8];
            float4 bb1 = *(const float4*)&Bs[kk][tx * 8 + 4];
            float a[8] = {aa0.x, aa0.y, aa0.z, aa0.w, aa1.x, aa1.y, aa1.z, aa1.w};
            float b[8] = {bb0.x, bb0.y, bb0.z, bb0.w, bb1.x, bb1.y, bb1.z, bb1.w};
#pragma unroll
            for (int i = 0; i < 8; i++)
#pragma unroll
                for (int j = 0; j < 8; j++) acc[i][j] += a[i] * b[j];
        }
    }

    float4 bv0 = *(const float4*)&bias[n0 + tx * 8];
    float4 bv1 = *(const float4*)&bias[n0 + tx * 8 + 4];
    float bb[8] = {bv0.x, bv0.y, bv0.z, bv0.w, bv1.x, bv1.y, bv1.z, bv1.w};
#pragma unroll
    for (int i = 0; i < 8; i++) {
        float4 o0, o1;
        o0.x = acc[i][0] + bb[0]; o0.y = acc[i][1] + bb[1];
        o0.z = acc[i][2] + bb[2]; o0.w = acc[i][3] + bb[3];
        o1.x = acc[i][4] + bb[4]; o1.y = acc[i][5] + bb[5];
        o1.z = acc[i][6] + bb[6]; o1.w = acc[i][7] + bb[7];
        *(float4*)&C[(m0 + ty * 8 + i) * 1024 + n0 + tx * 8] = o0;
        *(float4*)&C[(m0 + ty * 8 + i) * 1024 + n0 + tx * 8 + 4] = o1;
    }
}

// ---------------------------------------------------------------------------
// Tensor-core recurrence (mma.sync bf16x3).
// 128 CTAs = 2 dirs x 8 batch-tiles(16 rows) x 8 unit-tiles(32 units x 4 gates)
// 256 threads (8 warps). Warp w: M=16, N=16 (permuted cols 16w..16w+15), K=256.
// R^T in SMEM bf16 hi/lo [128 n][264 k]; h images copied per step from global.
// ---------------------------------------------------------------------------
#define RP 264                      // k pitch (bf16) -> 528 B rows
#define OFF_RHI 0                   // 128*528 = 67584
#define OFF_RLO 67584
#define OFF_HHI 135168              // 16*528 = 8448
#define OFF_HLO 143616
#define OFF_Z   152064              // 16*132*4 = 8448
#define REC_SMEM_TOTAL (152064 + 8448)

__device__ __forceinline__ void group_barrier(int grp, unsigned* s_sense) {
    __syncthreads();
    if (threadIdx.x == 0) {
        unsigned ls = *s_sense ^ 1u;
        *s_sense = ls;
        __threadfence();
        unsigned v = atomicAdd(&g_cnt[grp], 1u);
        if (v == 7u) {
            g_cnt[grp] = 0u;
            __threadfence();
            g_sns[grp] = ls;
        } else {
            while (g_sns[grp] != ls) { }
        }
    }
    __syncthreads();
}

__global__ __launch_bounds__(256, 1) void rec_mma_kernel(
    const float* __restrict__ rfw, const float* __restrict__ rbw, int layer)
{
    extern __shared__ unsigned char smx[];
    float* zsm = (float*)(smx + OFF_Z);

    const int bx  = blockIdx.x;
    const int dir = bx >> 6;
    const int ut  = bx & 7;
    const int grp = bx >> 3;            // dir*8 + batch_tile
    const int bt  = (bx >> 3) & 7;
    const int b0  = bt * 16;
    const int u0  = ut * 32;

    const float* __restrict__ R  = (dir ? rbw : rfw) + layer * 262144;
    const float* __restrict__ xz = g_xz[dir];
    float* __restrict__ outp     = layer ? g_out2[dir] : g_out1[dir];

    const int tid  = threadIdx.x;
    const int lane = tid & 31;
    const int w    = tid >> 5;

    __shared__ unsigned s_sense;
    if (tid == 0) s_sense = g_sns[grp];

    // ---- load R slice -> R^T bf16 hi/lo planes (permuted cols) ----
    // ci = q*32+uu  <- orig col q*256 + u0 + uu ; store [ci][k]
    for (int i = tid; i < 128 * 256; i += 256) {
        int ci = i & 127;
        int k  = i >> 7;
        float rv = R[k * 1024 + (ci >> 5) * 256 + u0 + (ci & 31)];
        __nv_bfloat16 hi = __float2bfloat16(rv);
        __nv_bfloat16 lo = __float2bfloat16(rv - __bfloat162float(hi));
        *(__nv_bfloat16*)(smx + OFF_RHI + (ci * RP + k) * 2) = hi;
        *(__nv_bfloat16*)(smx + OFF_RLO + (ci * RP + k) * 2) = lo;
    }

    // ---- zero phase-0 h image (all 8 CTAs of the group write zeros: benign)
    {
        uint4* dst = (uint4*)g_himg[dir][0][bt];
        for (int i = tid; i < 1056; i += 256) dst[i] = make_uint4(0, 0, 0, 0);
    }
    __threadfence();
    group_barrier(grp, &s_sense);

    // ---- per-thread ldmatrix offsets (byte) ----
    const int arow  = (lane & 7) + 8 * ((lane >> 3) & 1);
    const int aoff  = arow * (RP * 2) + 8 * (lane >> 4) * 2;
    const int n0w   = w * 16;
    const int brow  = n0w + (lane & 7) + 8 * ((lane >> 4) & 1);
    const int boff  = brow * (RP * 2) + 8 * ((lane >> 3) & 1) * 2;
    const uint32_t aHi = smem_u32(smx + OFF_HHI) + aoff;
    const uint32_t aLo = smem_u32(smx + OFF_HLO) + aoff;
    const uint32_t bHi = smem_u32(smx + OFF_RHI) + boff;
    const uint32_t bLo = smem_u32(smx + OFF_RLO) + boff;

    // xz C-init mapping: warp cols 16w..16w+15 all in gate q=w>>1
    const int m_r   = lane >> 2;                       // frag row
    const int ccol  = 2 * (lane & 3);                  // frag col pair base
    const int gcol0 = (w >> 1) * 256 + u0 + 16 * (w & 1) + ccol;

    // gate-phase coordinates
    const int gr  = tid >> 4;            // row 0..15
    const int gu2 = (tid & 15) * 2;      // unit pair in 0..31
    float cst[2] = {0.0f, 0.0f};

    for (int s = 0; s < 256; s++) {
        const int t = dir ? (255 - s) : s;

        // C fragments initialized from xz (z = xz + h@R)
        float c0[4], c1[4];
        {
            const float* xb = xz + ((size_t)(b0 + m_r) * 256 + t) * 1024 + gcol0;
            const float* xb8 = xb + (size_t)8 * 256 * 1024;
            float2 v00 = *(const float2*)xb;
            float2 v01 = *(const float2*)(xb + 8);
            float2 v10 = *(const float2*)xb8;
            float2 v11 = *(const float2*)(xb8 + 8);
            c0[0] = v00.x; c0[1] = v00.y; c0[2] = v10.x; c0[3] = v10.y;
            c1[0] = v01.x; c1[1] = v01.y; c1[2] = v11.x; c1[3] = v11.y;
        }

        // copy h image (hi+lo planes, 16896 B) global -> smem
        {
            const uint4* src = (const uint4*)g_himg[dir][s & 1][bt];
            uint4* dst = (uint4*)(smx + OFF_HHI);
            for (int i = tid; i < 1056; i += 256) dst[i] = __ldcg(src + i);
        }
        __syncthreads();

        // 16 k-steps x (4 ldmatrix.x4 + 6 mma)
#pragma unroll 4
        for (int ks = 0; ks < 16; ks++) {
            uint32_t ah0, ah1, ah2, ah3, al0, al1, al2, al3;
            uint32_t bh0, bh1, bh2, bh3, bl0, bl1, bl2, bl3;
            LDSM4(ah0, ah1, ah2, ah3, aHi + 32 * ks);
            LDSM4(bh0, bh1, bh2, bh3, bHi + 32 * ks);
            LDSM4(al0, al1, al2, al3, aLo + 32 * ks);
            LDSM4(bl0, bl1, bl2, bl3, bLo + 32 * ks);
            MMA16816(c0[0], c0[1], c0[2], c0[3], ah0, ah1, ah2, ah3, bh0, bh1);
            MMA16816(c1[0], c1[1], c1[2], c1[3], ah0, ah1, ah2, ah3, bh2, bh3);
            MMA16816(c0[0], c0[1], c0[2], c0[3], al0, al1, al2, al3, bh0, bh1);
            MMA16816(c1[0], c1[1], c1[2], c1[3], al0, al1, al2, al3, bh2, bh3);
            MMA16816(c0[0], c0[1], c0[2], c0[3], ah0, ah1, ah2, ah3, bl0, bl1);
            MMA16816(c1[0], c1[1], c1[2], c1[3], ah0, ah1, ah2, ah3, bl2, bl3);
        }

        // stash z to SMEM for gate regrouping
        {
            int cb = n0w + ccol;
            *(float2*)&zsm[m_r * 132 + cb]       = make_float2(c0[0], c0[1]);
            *(float2*)&zsm[(m_r + 8) * 132 + cb] = make_float2(c0[2], c0[3]);
            *(float2*)&zsm[m_r * 132 + cb + 8]       = make_float2(c1[0], c1[1]);
            *(float2*)&zsm[(m_r + 8) * 132 + cb + 8] = make_float2(c1[2], c1[3]);
        }
        __syncthreads();

        // gates: thread owns (row gr, units gu2, gu2+1); c-state in registers
        {
            unsigned char* img = g_himg[dir][(s + 1) & 1][bt];
            float hv[2];
#pragma unroll
            for (int j = 0; j < 2; j++) {
                int uu = gu2 + j;
                float zi = zsm[gr * 132 + uu];
                float zf = zsm[gr * 132 + 32 + uu];
                float zg = zsm[gr * 132 + 64 + uu];
                float zo = zsm[gr * 132 + 96 + uu];
                float ig = sigf(zi);
                float fg = sigf(zf);
                float gg = tanhf_fast(zg);
                float og = sigf(zo);
                float cc = fg * cst[j] + ig * gg;
                cst[j] = cc;
                hv[j] = og * tanhf_fast(cc);
            }
            // fp32 output
            *(float2*)&outp[((size_t)(b0 + gr) * 256 + t) * 256 + u0 + gu2] =
                make_float2(hv[0], hv[1]);
            // bf16 hi/lo image for next phase
            __nv_bfloat16 h0 = __float2bfloat16(hv[0]);
            __nv_bfloat16 h1 = __float2bfloat16(hv[1]);
            __nv_bfloat16 l0 = __float2bfloat16(hv[0] - __bfloat162float(h0));
            __nv_bfloat16 l1 = __float2bfloat16(hv[1] - __bfloat162float(h1));
            uint32_t whi = (uint32_t)__bfloat16_as_ushort(h0)
                         | ((uint32_t)__bfloat16_as_ushort(h1) << 16);
            uint32_t wlo = (uint32_t)__bfloat16_as_ushort(l0)
                         | ((uint32_t)__bfloat16_as_ushort(l1) << 16);
            int cidx = u0 + gu2;
            *(uint32_t*)(img + (gr * RP + cidx) * 2)        = whi;
            *(uint32_t*)(img + 8448 + (gr * RP + cidx) * 2) = wlo;
        }

        __threadfence();
        group_barrier(grp, &s_sense);
    }
}

// ---------------------------------------------------------------------------
// Merge: out = 0.5 * (out2f + out1f + out2b + out1b)  (residual + average)
// ---------------------------------------------------------------------------
__global__ __launch_bounds__(256) void merge_kernel(float4* __restrict__ out) {
    int i = blockIdx.x * blockDim.x + threadIdx.x;
    const float4* a = (const float4*)g_out1[0];
    const float4* b = (const float4*)g_out2[0];
    const float4* c = (const float4*)g_out1[1];
    const float4* d = (const float4*)g_out2[1];
    float4 va = a[i], vb = b[i], vc = c[i], vd = d[i];
    float4 o;
    o.x = 0.5f * (va.x + vb.x + vc.x + vd.x);
    o.y = 0.5f * (va.y + vb.y + vc.y + vd.y);
    o.z = 0.5f * (va.z + vb.z + vc.z + vd.z);
    o.w = 0.5f * (va.w + vb.w + vc.w + vd.w);
    out[i] = o;
}

// ---------------------------------------------------------------------------
extern "C" void kernel_launch(void* const* d_in, const int* in_sizes, int n_in,
                              void* d_out, int out_size) {
    (void)in_sizes; (void)n_in; (void)out_size;
    const float* x   = (const float*)d_in[0];
    const float* kfw = (const float*)d_in[1];
    const float* rfw = (const float*)d_in[2];
    const float* bfw = (const float*)d_in[3];
    const float* kbw = (const float*)d_in[4];
    const float* rbw = (const float*)d_in[5];
    const float* bbw = (const float*)d_in[6];
    float* out = (float*)d_out;

    cudaFuncSetAttribute(rec_mma_kernel,
                         cudaFuncAttributeMaxDynamicSharedMemorySize,
                         REC_SMEM_TOTAL);

    dim3 gg(8, 256, 2);
    gemm_xz_kernel<<<gg, 256>>>(x, kfw, kbw, bfw, bbw, 0);
    rec_mma_kernel<<<128, 256, REC_SMEM_TOTAL>>>(rfw, rbw, 0);
    gemm_xz_kernel<<<gg, 256>>>(x, kfw, kbw, bfw, bbw, 1);
    rec_mma_kernel<<<128, 256, REC_SMEM_TOTAL>>>(rfw, rbw, 1);
    merge_kernel<<<8192, 256>>>((float4*)out);
}